// round 6
// baseline (speedup 1.0000x reference)
#include <cuda_runtime.h>
#include <math.h>

// DistanceTransformLoss: BCE-with-logits mean + sqrt(border) where
// border = sum(pred_bin * dist) / count_nonzero and
// dist[i] = min(H, |i - nearest target row in column|)   (exact identity of
// the two-pass grassfire transform with init=H).
//
// Shapes: predictions/targets (32, 1, 1024, 1024) float32. Output: 1 float.

#define HH 1024
#define WW 1024
#define NELEM (32ull * 1024ull * 1024ull)
#define DINF (1 << 20)
#define NBLOCKS 256

// Accumulators. Zero at module load; the last finishing block resets them
// after computing the output, so every launch / graph replay starts from
// zero. Deterministic: the final value is independent of block order.
__device__ double g_bce;
__device__ double g_total;
__device__ unsigned long long g_count;
__device__ unsigned g_done;

// 256 blocks x 512 threads, 2 blocks/SM (all 256 co-resident in one wave:
// tails overlap, no wave quantization). Block: image n = b>>3, 128-column
// group cg = b&7, full H. 16 warps; warp w -> 64-row band [64w, 64w+64),
// lane -> 4 consecutive columns via float4 (warp row-load = 512B contiguous).
// Column state = 64-bit masks. Cross-band carries: min-plus shuffle scans
// over 16 chunks (width-16 segments, 2 columns per warp pass).
__global__ __launch_bounds__(512, 2)
void dtl_main_kernel(const float* __restrict__ pred,
                     const float* __restrict__ tgt,
                     float* __restrict__ out) {
    __shared__ int sA[128][17];   // [column][chunk]
    __shared__ int sB[128][17];
    __shared__ float sBce[16];
    __shared__ float sTot[16];
    __shared__ int   sCnt[16];

    const int lane = threadIdx.x & 31;
    const int w    = threadIdx.x >> 5;    // 0..15, band index
    const int n    = blockIdx.x >> 3;
    const int cg   = blockIdx.x & 7;

    const size_t base = (size_t)n * HH * WW + (size_t)(w << 6) * WW
                      + (size_t)(cg << 7) + (size_t)(lane << 2);
    const float4* tp4 = (const float4*)(tgt + base);
    const float4* pp4 = (const float4*)(pred + base);

    // ---- Load loop 1: targets -> 4 x 64-bit masks ----
    unsigned long long m[4] = {0ull, 0ull, 0ull, 0ull};
    #pragma unroll 8
    for (int j = 0; j < 64; j++) {
        float4 t4 = __ldcs(tp4 + j * (WW / 4));
        m[0] |= (unsigned long long)(t4.x == 1.0f) << j;
        m[1] |= (unsigned long long)(t4.y == 1.0f) << j;
        m[2] |= (unsigned long long)(t4.z == 1.0f) << j;
        m[3] |= (unsigned long long)(t4.w == 1.0f) << j;
    }

    // Band summaries (no barrier yet):
    //  A = dist from next band's row 0 up to this band's last 1
    //  B = dist from prev band's row 63 down to this band's first 1
    #pragma unroll
    for (int c = 0; c < 4; c++) {
        sA[4 * lane + c][w] = m[c] ? (__clzll(m[c]) + 1) : DINF;
        sB[4 * lane + c][w] = m[c] ? __ffsll(m[c])       : DINF;
    }

    // ---- Load loop 2: predictions -> BCE + pb masks ----
    unsigned long long pb[4] = {0ull, 0ull, 0ull, 0ull};
    float bce0 = 0.0f, bce1 = 0.0f;
    #pragma unroll 8
    for (int j = 0; j < 64; j++) {
        float4 p4 = __ldcs(pp4 + j * (WW / 4));
        {
            float p = p4.x; pb[0] |= (unsigned long long)(p > 0.0f) << j;
            float t = (float)((m[0] >> j) & 1ull);
            bce0 += fmaxf(p, 0.0f) - p * t + __logf(1.0f + __expf(-fabsf(p)));
        }
        {
            float p = p4.y; pb[1] |= (unsigned long long)(p > 0.0f) << j;
            float t = (float)((m[1] >> j) & 1ull);
            bce1 += fmaxf(p, 0.0f) - p * t + __logf(1.0f + __expf(-fabsf(p)));
        }
        {
            float p = p4.z; pb[2] |= (unsigned long long)(p > 0.0f) << j;
            float t = (float)((m[2] >> j) & 1ull);
            bce0 += fmaxf(p, 0.0f) - p * t + __logf(1.0f + __expf(-fabsf(p)));
        }
        {
            float p = p4.w; pb[3] |= (unsigned long long)(p > 0.0f) << j;
            float t = (float)((m[3] >> j) & 1ull);
            bce1 += fmaxf(p, 0.0f) - p * t + __logf(1.0f + __expf(-fabsf(p)));
        }
    }
    float bce = bce0 + bce1;

    __syncthreads();

    // ---- Cross-band carries: shuffle min-scans over 16 chunks ----
    // Warp pass handles 2 columns: lanes 0-15 -> chunks of col0, 16-31 -> col1.
    // U[ch]  = min_{v<ch}(A_v + 64*(ch-1-v)) = exclPrefixMin(A_v-64v) + 64*(ch-1)
    // Dn[ch] = min_{v>ch}(B_v + 64*(v-1-ch)) = exclSuffixMin(B_v+64v) - 64*(ch+1)
    {
        const int half = lane >> 4;       // 0 or 1
        const int ch   = lane & 15;       // chunk index
        #pragma unroll
        for (int i = 0; i < 4; i++) {
            const int col = 8 * w + 2 * i + half;

            int a = sA[col][ch] - 64 * ch;
            #pragma unroll
            for (int o = 1; o < 16; o <<= 1) {
                int x = __shfl_up_sync(0xffffffffu, a, o, 16);
                if (ch >= o) a = min(a, x);
            }
            int ea = __shfl_up_sync(0xffffffffu, a, 1, 16);
            if (ch == 0) ea = DINF;

            int b = sB[col][ch] + 64 * ch;
            #pragma unroll
            for (int o = 1; o < 16; o <<= 1) {
                int x = __shfl_down_sync(0xffffffffu, b, o, 16);
                if (ch < 16 - o) b = min(b, x);
            }
            int eb = __shfl_down_sync(0xffffffffu, b, 1, 16);
            if (ch == 15) eb = DINF;

            sA[col][ch] = ea + 64 * (ch - 1);   // U
            sB[col][ch] = eb - 64 * (ch + 1);   // Dn
        }
    }
    __syncthreads();

    // ---- Penalty: sparse iteration over set bits of q = pb & ~m ----
    // penalty != 0  <=>  pred>0 and dist!=0  <=>  bit of q
    float tot = 0.0f;
    int cnt = 0;
    #pragma unroll
    for (int c = 0; c < 4; c++) {
        const int U  = sA[4 * lane + c][w];
        const int Dn = sB[4 * lane + c][w];
        const unsigned long long mc = m[c];
        unsigned long long q = pb[c] & ~mc;
        cnt += __popcll(q);
        while (q) {
            int j = __ffsll(q) - 1;
            q &= q - 1ull;
            unsigned long long mlow  = mc << (63 - j);
            unsigned long long mhigh = mc >> j;
            int dup   = mlow  ? __clzll(mlow)        : U + j;
            int ddown = mhigh ? (__ffsll(mhigh) - 1) : Dn + (63 - j);
            tot += (float)min(min(dup, ddown), HH);
        }
    }

    // ---- Reduce: warp shfl -> smem -> warp0 shfl -> global double atomics ----
    #pragma unroll
    for (int o = 16; o > 0; o >>= 1) {
        bce += __shfl_xor_sync(0xffffffffu, bce, o);
        tot += __shfl_xor_sync(0xffffffffu, tot, o);
        cnt += __shfl_xor_sync(0xffffffffu, cnt, o);
    }
    if (lane == 0) {
        sBce[w] = bce;
        sTot[w] = tot;
        sCnt[w] = cnt;
    }
    __syncthreads();
    if (w == 0 && lane == 0) {
        float b = 0.0f, tt = 0.0f;
        int c = 0;
        #pragma unroll
        for (int v = 0; v < 16; v++) { b += sBce[v]; tt += sTot[v]; c += sCnt[v]; }
        atomicAdd(&g_bce, (double)b);
        atomicAdd(&g_total, (double)tt);
        atomicAdd(&g_count, (unsigned long long)c);

        // Completion ticket; last block finalizes and resets.
        __threadfence();
        unsigned ticket = atomicAdd(&g_done, 1u);
        if (ticket == NBLOCKS - 1) {
            __threadfence();
            double bsum = atomicAdd(&g_bce, 0.0);
            double tsum = atomicAdd(&g_total, 0.0);
            double csum = (double)atomicAdd(&g_count, 0ull);
            double border = (tsum == 0.0) ? 0.0 : tsum / fmax(csum, 1.0);
            out[0] = (float)(bsum / (double)NELEM + sqrt(border));
            // Reset for next launch / graph replay (entry invariant: zero).
            atomicExch((unsigned long long*)&g_bce, 0ull);
            atomicExch((unsigned long long*)&g_total, 0ull);
            atomicExch(&g_count, 0ull);
            atomicExch(&g_done, 0u);
        }
    }
}

extern "C" void kernel_launch(void* const* d_in, const int* in_sizes, int n_in,
                              void* d_out, int out_size) {
    const float* pred = (const float*)d_in[0];
    const float* tgt  = (const float*)d_in[1];
    float* out = (float*)d_out;

    // 32 images x 8 column-groups of 128 columns = 256 blocks
    dtl_main_kernel<<<NBLOCKS, 512>>>(pred, tgt, out);
}

// round 7
// speedup vs baseline: 1.2230x; 1.2230x over previous
#include <cuda_runtime.h>
#include <math.h>

// DistanceTransformLoss: BCE-with-logits mean + sqrt(border) where
// border = sum(pred_bin * dist) / count_nonzero and
// dist[i] = min(H, |i - nearest target row in column|)   (exact identity of
// the two-pass grassfire transform with init=H).
//
// Shapes: predictions/targets (32, 1, 1024, 1024) float32. Output: 1 float.

#define HH 1024
#define WW 1024
#define NELEM (32ull * 1024ull * 1024ull)
#define DINF (1 << 20)
#define NBLOCKS 256

// Accumulators. Zero at module load; the last finishing block resets them
// after computing the output, so every launch / graph replay starts from
// zero. Deterministic: final value independent of block order.
__device__ double g_bce;
__device__ double g_total;
__device__ unsigned long long g_count;
__device__ unsigned g_done;

// 256 blocks x 512 threads, 2 blocks/SM: all 256 blocks co-resident in one
// wave, so each block's ALU tail overlaps its SM-mate's load phase.
// Block: image n = b>>3, 128-column group cg = b&7, full H=1024.
// 16 warps; warp w -> 64-row band [64w, 64w+64) handled as TWO 32-row
// chunks (2w, 2w+1). lane -> 4 consecutive columns via float4 (warp
// row-load = 512B contiguous). ALL mask math is 32-bit (R6's 64-bit masks
// doubled ALU-pipe pressure to 55% and regressed).
__global__ __launch_bounds__(512, 2)
void dtl_main_kernel(const float* __restrict__ pred,
                     const float* __restrict__ tgt,
                     float* __restrict__ out) {
    __shared__ int sA[128][33];   // [column][chunk 0..31]
    __shared__ int sB[128][33];
    __shared__ float sBce[16];
    __shared__ float sTot[16];
    __shared__ int   sCnt[16];

    const int lane = threadIdx.x & 31;
    const int w    = threadIdx.x >> 5;    // 0..15, band index
    const int n    = blockIdx.x >> 3;
    const int cg   = blockIdx.x & 7;

    const size_t base = (size_t)n * HH * WW + (size_t)(w << 6) * WW
                      + (size_t)(cg << 7) + (size_t)(lane << 2);
    const float4* tp4 = (const float4*)(tgt + base);
    const float4* pp4 = (const float4*)(pred + base);

    // ---- Load targets: rows 0-31 of band -> mlo, rows 32-63 -> mhi ----
    unsigned mlo[4] = {0u,0u,0u,0u}, mhi[4] = {0u,0u,0u,0u};
    #pragma unroll 8
    for (int j = 0; j < 32; j++) {
        float4 t4 = __ldcs(tp4 + j * (WW / 4));
        mlo[0] |= (t4.x == 1.0f ? 1u : 0u) << j;
        mlo[1] |= (t4.y == 1.0f ? 1u : 0u) << j;
        mlo[2] |= (t4.z == 1.0f ? 1u : 0u) << j;
        mlo[3] |= (t4.w == 1.0f ? 1u : 0u) << j;
    }
    #pragma unroll 8
    for (int j = 0; j < 32; j++) {
        float4 t4 = __ldcs(tp4 + (j + 32) * (WW / 4));
        mhi[0] |= (t4.x == 1.0f ? 1u : 0u) << j;
        mhi[1] |= (t4.y == 1.0f ? 1u : 0u) << j;
        mhi[2] |= (t4.z == 1.0f ? 1u : 0u) << j;
        mhi[3] |= (t4.w == 1.0f ? 1u : 0u) << j;
    }

    // Chunk summaries (no barrier yet):
    //  A = dist from next chunk's row 0 up to this chunk's last 1
    //  B = dist from prev chunk's row 31 down to this chunk's first 1
    #pragma unroll
    for (int c = 0; c < 4; c++) {
        const int col = 4 * lane + c;
        sA[col][2 * w]     = mlo[c] ? (__clz(mlo[c]) + 1) : DINF;
        sB[col][2 * w]     = mlo[c] ? __ffs(mlo[c])       : DINF;
        sA[col][2 * w + 1] = mhi[c] ? (__clz(mhi[c]) + 1) : DINF;
        sB[col][2 * w + 1] = mhi[c] ? __ffs(mhi[c])       : DINF;
    }

    // ---- Load predictions: BCE + pb masks (32-bit, two half-band loops) ----
    unsigned pblo[4] = {0u,0u,0u,0u}, pbhi[4] = {0u,0u,0u,0u};
    float bce0 = 0.0f, bce1 = 0.0f;
    #pragma unroll 8
    for (int j = 0; j < 32; j++) {
        float4 p4 = __ldcs(pp4 + j * (WW / 4));
        { float p = p4.x; pblo[0] |= (p > 0.0f ? 1u : 0u) << j;
          float t = (float)((mlo[0] >> j) & 1u);
          bce0 += fmaxf(p, 0.0f) - p * t + __logf(1.0f + __expf(-fabsf(p))); }
        { float p = p4.y; pblo[1] |= (p > 0.0f ? 1u : 0u) << j;
          float t = (float)((mlo[1] >> j) & 1u);
          bce1 += fmaxf(p, 0.0f) - p * t + __logf(1.0f + __expf(-fabsf(p))); }
        { float p = p4.z; pblo[2] |= (p > 0.0f ? 1u : 0u) << j;
          float t = (float)((mlo[2] >> j) & 1u);
          bce0 += fmaxf(p, 0.0f) - p * t + __logf(1.0f + __expf(-fabsf(p))); }
        { float p = p4.w; pblo[3] |= (p > 0.0f ? 1u : 0u) << j;
          float t = (float)((mlo[3] >> j) & 1u);
          bce1 += fmaxf(p, 0.0f) - p * t + __logf(1.0f + __expf(-fabsf(p))); }
    }
    #pragma unroll 8
    for (int j = 0; j < 32; j++) {
        float4 p4 = __ldcs(pp4 + (j + 32) * (WW / 4));
        { float p = p4.x; pbhi[0] |= (p > 0.0f ? 1u : 0u) << j;
          float t = (float)((mhi[0] >> j) & 1u);
          bce0 += fmaxf(p, 0.0f) - p * t + __logf(1.0f + __expf(-fabsf(p))); }
        { float p = p4.y; pbhi[1] |= (p > 0.0f ? 1u : 0u) << j;
          float t = (float)((mhi[1] >> j) & 1u);
          bce1 += fmaxf(p, 0.0f) - p * t + __logf(1.0f + __expf(-fabsf(p))); }
        { float p = p4.z; pbhi[2] |= (p > 0.0f ? 1u : 0u) << j;
          float t = (float)((mhi[2] >> j) & 1u);
          bce0 += fmaxf(p, 0.0f) - p * t + __logf(1.0f + __expf(-fabsf(p))); }
        { float p = p4.w; pbhi[3] |= (p > 0.0f ? 1u : 0u) << j;
          float t = (float)((mhi[3] >> j) & 1u);
          bce1 += fmaxf(p, 0.0f) - p * t + __logf(1.0f + __expf(-fabsf(p))); }
    }
    float bce = bce0 + bce1;

    __syncthreads();

    // ---- Cross-chunk carries: full-width-32 shuffle min-scans ----
    // Warp w scans columns 8w..8w+7; lane = chunk index (32 chunks).
    // U[ch]  = min_{v<ch}(A_v + 32*(ch-1-v)) = exclPrefixMin(A_v-32v) + 32*(ch-1)
    // Dn[ch] = min_{v>ch}(B_v + 32*(v-1-ch)) = exclSuffixMin(B_v+32v) - 32*(ch+1)
    #pragma unroll
    for (int i = 0; i < 8; i++) {
        const int k = 8 * w + i;

        int a = sA[k][lane] - 32 * lane;
        #pragma unroll
        for (int o = 1; o < 32; o <<= 1) {
            int x = __shfl_up_sync(0xffffffffu, a, o);
            if (lane >= o) a = min(a, x);
        }
        int ea = __shfl_up_sync(0xffffffffu, a, 1);
        if (lane == 0) ea = DINF;

        int b = sB[k][lane] + 32 * lane;
        #pragma unroll
        for (int o = 1; o < 32; o <<= 1) {
            int x = __shfl_down_sync(0xffffffffu, b, o);
            if (lane < 32 - o) b = min(b, x);
        }
        int eb = __shfl_down_sync(0xffffffffu, b, 1);
        if (lane == 31) eb = DINF;

        sA[k][lane] = ea + 32 * (lane - 1);   // U for chunk=lane, column k
        sB[k][lane] = eb - 32 * (lane + 1);   // Dn
    }
    __syncthreads();

    // ---- Penalty: sparse iteration over set bits of q = pb & ~m ----
    // penalty != 0  <=>  pred>0 and dist!=0  <=>  bit of q
    float tot = 0.0f;
    int cnt = 0;
    #pragma unroll
    for (int c = 0; c < 4; c++) {
        const int col = 4 * lane + c;
        #pragma unroll
        for (int h = 0; h < 2; h++) {
            const unsigned mc = h ? mhi[c] : mlo[c];
            unsigned q = (h ? pbhi[c] : pblo[c]) & ~mc;
            const int U  = sA[col][2 * w + h];
            const int Dn = sB[col][2 * w + h];
            cnt += __popc(q);
            while (q) {
                int j = __ffs(q) - 1;
                q &= q - 1u;
                unsigned xlow  = mc << (31 - j);
                unsigned xhigh = mc >> j;
                int dup   = xlow  ? __clz(xlow)        : U + j;
                int ddown = xhigh ? (__ffs(xhigh) - 1) : Dn + (31 - j);
                tot += (float)min(min(dup, ddown), HH);
            }
        }
    }

    // ---- Reduce: warp shfl -> smem -> thread0 -> global double atomics ----
    #pragma unroll
    for (int o = 16; o > 0; o >>= 1) {
        bce += __shfl_xor_sync(0xffffffffu, bce, o);
        tot += __shfl_xor_sync(0xffffffffu, tot, o);
        cnt += __shfl_xor_sync(0xffffffffu, cnt, o);
    }
    if (lane == 0) {
        sBce[w] = bce;
        sTot[w] = tot;
        sCnt[w] = cnt;
    }
    __syncthreads();
    if (w == 0 && lane == 0) {
        float b = 0.0f, tt = 0.0f;
        int c = 0;
        #pragma unroll
        for (int v = 0; v < 16; v++) { b += sBce[v]; tt += sTot[v]; c += sCnt[v]; }
        atomicAdd(&g_bce, (double)b);
        atomicAdd(&g_total, (double)tt);
        atomicAdd(&g_count, (unsigned long long)c);

        // Completion ticket; last block finalizes and resets.
        __threadfence();
        unsigned ticket = atomicAdd(&g_done, 1u);
        if (ticket == NBLOCKS - 1) {
            __threadfence();
            double bsum = atomicAdd(&g_bce, 0.0);
            double tsum = atomicAdd(&g_total, 0.0);
            double csum = (double)atomicAdd(&g_count, 0ull);
            double border = (tsum == 0.0) ? 0.0 : tsum / fmax(csum, 1.0);
            out[0] = (float)(bsum / (double)NELEM + sqrt(border));
            // Reset for next launch / graph replay (entry invariant: zero).
            atomicExch((unsigned long long*)&g_bce, 0ull);
            atomicExch((unsigned long long*)&g_total, 0ull);
            atomicExch(&g_count, 0ull);
            atomicExch(&g_done, 0u);
        }
    }
}

extern "C" void kernel_launch(void* const* d_in, const int* in_sizes, int n_in,
                              void* d_out, int out_size) {
    const float* pred = (const float*)d_in[0];
    const float* tgt  = (const float*)d_in[1];
    float* out = (float*)d_out;

    // 32 images x 8 column-groups of 128 columns = 256 blocks
    dtl_main_kernel<<<NBLOCKS, 512>>>(pred, tgt, out);
}